// round 10
// baseline (speedup 1.0000x reference)
#include <cuda_runtime.h>
#include <math.h>

// ---------------- problem constants ----------------
#define B_N   4096
#define D1    200
#define WIN   400
#define WOUT  392
#define OC    32
#define FW    9
#define T_N   288
#define FCL   12544
#define EPSf  1e-5f

#define NGROUP 8
#define MPERG  50
#define NREL   500
#define RPAD   512
#define GSTR   416     // padded G row stride
#define WB     104     // w'-columns per k_G block-x (4 x-blocks cover 416)

// ---------------- scratch (__device__ globals) ----------------
__device__ float g_consts[8];              // [0]=CbCz+fc2_b, [1]=a0, [2]=c0, [3]=Ctot, [4]=bias
__device__ float g_wEffP[NGROUP][FCL];
__device__ float g_wEffS[FCL];             // s1[o] * wEff
__device__ float g_ckp[49];                // Ck per-block partials
__device__ float g_ktab[RPAD * T_N];       // per-relation conv filters (+bias)
__device__ float g_G[RPAD * GSTR];         // per-relation score vectors
__device__ float g_srp[4][RPAD];           // G row-sum partials per w'-block

// ---------------- K1: wEff partials (blocks 0..103) + ktab GEMM (blocks 104..247) ----------
__global__ __launch_bounds__(256) void k_main(const float* __restrict__ fc_w,
                                              const float* __restrict__ fc1_w,
                                              const float* __restrict__ bn2_g,
                                              const float* __restrict__ bn2_v,
                                              const float* __restrict__ fc2_w,
                                              const float* __restrict__ R,
                                              const float* __restrict__ fc1_b)
{
    int bid = blockIdx.x, tid = threadIdx.x;
    if (bid < 104) {
        int g = bid / 13, fb = bid % 13;
        __shared__ float vs[MPERG];
        if (tid < MPERG) {
            int m = g * MPERG + tid;
            float s2 = bn2_g[m] * rsqrtf(bn2_v[m] + EPSf);
            vs[tid] = fc2_w[m] * s2;
        }
        __syncthreads();
        int f4 = fb * 256 + tid;
        if (f4 >= FCL / 4) return;
        const float4* src = reinterpret_cast<const float4*>(fc_w)
                          + (size_t)g * MPERG * (FCL / 4) + f4;
        float4 acc = make_float4(0.f, 0.f, 0.f, 0.f);
#pragma unroll 5
        for (int m = 0; m < MPERG; m++) {
            float vm = vs[m];
            float4 w = src[(size_t)m * (FCL / 4)];
            acc.x = fmaf(vm, w.x, acc.x);
            acc.y = fmaf(vm, w.y, acc.y);
            acc.z = fmaf(vm, w.z, acc.z);
            acc.w = fmaf(vm, w.w, acc.w);
        }
        *reinterpret_cast<float4*>(&g_wEffP[g][f4 * 4]) = acc;
    } else {
        // ---- ktab[512,288] = clamp(R) @ fc1_w^T + fc1_b ----
        __shared__ float Xs[32][9];
        __shared__ float Ws[8][32];
        int n = bid - 104;
        int n0 = (n % 9) * 32, m0 = (n / 9) * 32;
        int rg = tid >> 4, cg = tid & 15;
        int xr = tid >> 3, xk = tid & 7;
        int wk = tid >> 5, wc = tid & 31;

        int rrow = m0 + xr; if (rrow >= NREL) rrow = NREL - 1;
        const float* xsrc = R + (size_t)rrow * D1;
        const float* wsrc = fc1_w + (size_t)(n0 + wc) * D1;

        float rx = xsrc[xk];
        float rw = wsrc[wk];
        float acc00 = 0.f, acc01 = 0.f, acc10 = 0.f, acc11 = 0.f;
        for (int c = 0; c < 25; c++) {
            __syncthreads();
            Xs[xr][xk] = rx;
            Ws[wk][wc] = rw;
            __syncthreads();
            if (c + 1 < 25) {
                int d0 = (c + 1) * 8;
                rx = xsrc[d0 + xk];
                rw = wsrc[d0 + wk];
            }
#pragma unroll
            for (int kk = 0; kk < 8; kk++) {
                float x0 = Xs[rg * 2][kk], x1 = Xs[rg * 2 + 1][kk];
                float2 w2 = *reinterpret_cast<const float2*>(&Ws[kk][cg * 2]);
                acc00 = fmaf(x0, w2.x, acc00);
                acc01 = fmaf(x0, w2.y, acc01);
                acc10 = fmaf(x1, w2.x, acc10);
                acc11 = fmaf(x1, w2.y, acc11);
            }
        }
        float2 b2 = *reinterpret_cast<const float2*>(fc1_b + n0 + cg * 2);
        *reinterpret_cast<float2*>(g_ktab + (size_t)(m0 + rg * 2) * T_N + n0 + cg * 2) =
            make_float2(acc00 + b2.x, acc01 + b2.y);
        *reinterpret_cast<float2*>(g_ktab + (size_t)(m0 + rg * 2 + 1) * T_N + n0 + cg * 2) =
            make_float2(acc10 + b2.x, acc11 + b2.y);
    }
}

// ---------------- K2: reduce -> wEffS + Ck partials; block 0 computes consts ----------------
__global__ __launch_bounds__(256) void k_reduce(const float* __restrict__ bn1_g,
                                                const float* __restrict__ bn1_b,
                                                const float* __restrict__ bn1_m,
                                                const float* __restrict__ bn1_v,
                                                const float* __restrict__ bn0_g,
                                                const float* __restrict__ bn0_b,
                                                const float* __restrict__ bn0_m,
                                                const float* __restrict__ bn0_v,
                                                const float* __restrict__ bn2_g,
                                                const float* __restrict__ bn2_b,
                                                const float* __restrict__ bn2_m,
                                                const float* __restrict__ bn2_v,
                                                const float* __restrict__ fc2_w,
                                                const float* __restrict__ fc2_b,
                                                const float* __restrict__ fc_b,
                                                const float* __restrict__ bias)
{
    __shared__ float red[256];
    int tid = threadIdx.x;
    int f = blockIdx.x * 256 + tid;
    int o = f / WOUT;
    float s1 = bn1_g[o] * rsqrtf(bn1_v[o] + EPSf);
    float t1 = bn1_b[o] - bn1_m[o] * s1;
    float s = 0.f;
#pragma unroll
    for (int g = 0; g < NGROUP; g++) s += g_wEffP[g][f];
    g_wEffS[f] = s1 * s;
    red[tid] = t1 * s;
    __syncthreads();
    for (int st = 128; st > 0; st >>= 1) {
        if (tid < st) red[tid] += red[tid + st];
        __syncthreads();
    }
    if (tid == 0) g_ckp[blockIdx.x] = red[0];

    if (blockIdx.x == 0) {
        __syncthreads();
        float l2;
        {
            int m = tid;
            float s2 = bn2_g[m] * rsqrtf(bn2_v[m] + EPSf);
            l2 = fc2_w[m] * (bn2_b[m] - bn2_m[m] * s2) + fc2_w[m] * s2 * fc_b[m];
        }
        if (tid < 144) {
            int m = tid + 256;
            float s2 = bn2_g[m] * rsqrtf(bn2_v[m] + EPSf);
            l2 += fc2_w[m] * (bn2_b[m] - bn2_m[m] * s2) + fc2_w[m] * s2 * fc_b[m];
        }
        red[tid] = l2;
        __syncthreads();
        for (int st = 128; st > 0; st >>= 1) {
            if (tid < st) red[tid] += red[tid + st];
            __syncthreads();
        }
        if (tid == 0) {
            g_consts[0] = red[0] + fc2_b[0];
            float a0 = bn0_g[0] * rsqrtf(bn0_v[0] + EPSf);
            g_consts[1] = a0;
            g_consts[2] = bn0_b[0] - bn0_m[0] * a0;
            g_consts[4] = bias[0];
        }
    }
}

// ---------------- K3: G = ktab @ A^T via smem band; plus Ctot in extra block row ------------
__global__ __launch_bounds__(512) void k_G()
{
    if (blockIdx.y == 32) {
        if (blockIdx.x != 0 || threadIdx.x >= 32) return;
        int l = threadIdx.x;
        float v = (l < 49) ? g_ckp[l] : 0.f;
        if (l < 17) v += g_ckp[l + 32];
#pragma unroll
        for (int off = 16; off > 0; off >>= 1)
            v += __shfl_xor_sync(0xFFFFFFFFu, v, off);
        if (l == 0) g_consts[3] = v + g_consts[0];
        return;
    }

    __shared__ float band[32][136];
    __shared__ float kt[16][288];

    int tid = threadIdx.x;
    int w0 = blockIdx.x * WB;
    int m0 = blockIdx.y * 16;

    {
        const float4* src = reinterpret_cast<const float4*>(g_ktab + (size_t)m0 * T_N);
        float4* dst = reinterpret_cast<float4*>(&kt[0][0]);
#pragma unroll
        for (int f4 = tid; f4 < 1152; f4 += 512) dst[f4] = src[f4];
    }
    for (int f4 = tid; f4 < 896; f4 += 512) {
        int o = f4 / 28, i4 = (f4 % 28) * 4;
        int gb = w0 - 8 + i4;
        const float* wsrc = g_wEffS + o * WOUT;
        float4 v;
        v.x = ((unsigned)(gb    ) < (unsigned)WOUT) ? wsrc[gb    ] : 0.f;
        v.y = ((unsigned)(gb + 1) < (unsigned)WOUT) ? wsrc[gb + 1] : 0.f;
        v.z = ((unsigned)(gb + 2) < (unsigned)WOUT) ? wsrc[gb + 2] : 0.f;
        v.w = ((unsigned)(gb + 3) < (unsigned)WOUT) ? wsrc[gb + 3] : 0.f;
        *reinterpret_cast<float4*>(&band[o][i4]) = v;
    }
    __syncthreads();

    int warp = tid >> 5, l = tid & 31;
    int base = l * 4;
    const float* ktr = kt[warp];

    float a0 = 0.f, a1 = 0.f, a2 = 0.f, a3 = 0.f;
#pragma unroll
    for (int o = 0; o < 32; o++) {
        float k9[9];
#pragma unroll
        for (int j = 0; j < 9; j++) k9[j] = ktr[o * FW + j];
        float4 wa = *reinterpret_cast<const float4*>(&band[o][base]);
        float4 wb = *reinterpret_cast<const float4*>(&band[o][base + 4]);
        float4 wc = *reinterpret_cast<const float4*>(&band[o][base + 8]);
        float w12[12] = {wa.x, wa.y, wa.z, wa.w, wb.x, wb.y, wb.z, wb.w,
                         wc.x, wc.y, wc.z, wc.w};
#pragma unroll
        for (int j = 0; j < 9; j++) {
            a0 = fmaf(k9[j], w12[8  - j], a0);
            a1 = fmaf(k9[j], w12[9  - j], a1);
            a2 = fmaf(k9[j], w12[10 - j], a2);
            a3 = fmaf(k9[j], w12[11 - j], a3);
        }
    }

    int r = m0 + warp;
    float sum;
    if (base < WB) {
        *reinterpret_cast<float4*>(g_G + (size_t)r * GSTR + w0 + base) =
            make_float4(a0, a1, a2, a3);
        sum = (a0 + a1) + (a2 + a3);
    } else {
        sum = 0.f;
    }
#pragma unroll
    for (int off = 16; off > 0; off >>= 1)
        sum += __shfl_xor_sync(0xFFFFFFFFu, sum, off);
    if (l == 0) g_srp[blockIdx.x][r] = sum;
}

// ---------------- K4: out[b] = tanh( a0*dot + c0*SG[r] + Ctot ) + bias ---------------------
// Warp-pair per output: warp p=0 does E1.G[0:200] (+ scalar terms in lanes>=25),
// warp p=1 does E2.G[200:400]. 8192 warps total -> ~2x resident warps vs R8,
// halving exposed DRAM latency per output. Combine via smem.
__global__ __launch_bounds__(256) void k_final(const int* __restrict__ e1_idx,
                                               const int* __restrict__ r_idx,
                                               const int* __restrict__ e2_idx,
                                               const float* __restrict__ E,
                                               float* __restrict__ out)
{
    __shared__ float sm[8];
    int w = threadIdx.x >> 5, l = threadIdx.x & 31;
    int pair = w >> 1, p = w & 1;
    int b = blockIdx.x * 4 + pair;
    int r = __ldg(r_idx + b);
    int ei = p ? __ldg(e2_idx + b) : __ldg(e1_idx + b);
    float a0 = g_consts[1], c0 = g_consts[2];

    float v;
    if (l < 25) {
        const float4* Ep = reinterpret_cast<const float4*>(E + (size_t)ei * D1);
        const float4* Gp = reinterpret_cast<const float4*>(g_G + (size_t)r * GSTR) + p * 50;
        float4 e0 = Ep[l], e1v = Ep[l + 25];
        float4 g0 = Gp[l], g1v = Gp[l + 25];
        float d0 = fmaf(e0.x,  g0.x,  fmaf(e0.y,  g0.y,  fmaf(e0.z,  g0.z,  e0.w  * g0.w)));
        float d1 = fmaf(e1v.x, g1v.x, fmaf(e1v.y, g1v.y, fmaf(e1v.z, g1v.z, e1v.w * g1v.w)));
        v = a0 * (d0 + d1);
    } else if (p == 0 && l < 29) {
        v = c0 * g_srp[l - 25][r];
    } else if (p == 0 && l == 29) {
        v = g_consts[3];
    } else {
        v = 0.f;
    }
#pragma unroll
    for (int off = 16; off > 0; off >>= 1)
        v += __shfl_xor_sync(0xFFFFFFFFu, v, off);
    if (l == 0) sm[w] = v;
    __syncthreads();
    if (threadIdx.x < 4) {
        int bb = blockIdx.x * 4 + threadIdx.x;
        out[bb] = tanhf(sm[2 * threadIdx.x] + sm[2 * threadIdx.x + 1]) + g_consts[4];
    }
}

// ---------------- launch ----------------
extern "C" void kernel_launch(void* const* d_in, const int* in_sizes, int n_in,
                              void* d_out, int out_size)
{
    const int*   e1   = (const int*)d_in[0];
    const int*   ridx = (const int*)d_in[1];
    const int*   e2   = (const int*)d_in[2];
    const float* E    = (const float*)d_in[3];
    const float* R    = (const float*)d_in[4];
    const float* bn0g = (const float*)d_in[5];
    const float* bn0b = (const float*)d_in[6];
    const float* bn0m = (const float*)d_in[7];
    const float* bn0v = (const float*)d_in[8];
    const float* fc1w = (const float*)d_in[9];
    const float* fc1b = (const float*)d_in[10];
    const float* bn1g = (const float*)d_in[11];
    const float* bn1b = (const float*)d_in[12];
    const float* bn1m = (const float*)d_in[13];
    const float* bn1v = (const float*)d_in[14];
    const float* fcw  = (const float*)d_in[15];
    const float* fcb  = (const float*)d_in[16];
    const float* bn2g = (const float*)d_in[17];
    const float* bn2b = (const float*)d_in[18];
    const float* bn2m = (const float*)d_in[19];
    const float* bn2v = (const float*)d_in[20];
    const float* fc2w = (const float*)d_in[21];
    const float* fc2b = (const float*)d_in[22];
    const float* bias = (const float*)d_in[23];
    float* out = (float*)d_out;

    k_main<<<248, 256>>>(fcw, fc1w, bn2g, bn2v, fc2w, R, fc1b);
    k_reduce<<<49, 256>>>(bn1g, bn1b, bn1m, bn1v,
                          bn0g, bn0b, bn0m, bn0v,
                          bn2g, bn2b, bn2m, bn2v,
                          fc2w, fc2b, fcb, bias);
    k_G<<<dim3(4, 33), 512>>>();
    k_final<<<B_N / 4, 256>>>(e1, ridx, e2, E, out);
}